// round 16
// baseline (speedup 1.0000x reference)
#include <cuda_runtime.h>
#include <cuda_fp16.h>
#include <cstdint>
#include <cstddef>

// ---------------------------------------------------------------------------
// Problem constants
// ---------------------------------------------------------------------------
constexpr int B_ = 8, N_ = 2048, D_ = 1024, H_ = 2048;
constexpr int MTOT = B_ * N_;      // 16384
constexpr int SEGLEN = 512;

// Scratch (device globals; allocations forbidden)
__device__ __half g_xh [(size_t)MTOT * D_];
__device__ __half g_w1h[(size_t)4 * D_ * H_];
__device__ __half g_w3h[(size_t)4 * D_ * H_];
__device__ __half g_w2h[(size_t)4 * H_ * D_];
__device__ __half g_h  [(size_t)MTOT * H_];

// ---------------------------------------------------------------------------
// Helpers
// ---------------------------------------------------------------------------
__device__ __forceinline__ uint32_t smem_u32(const void* p) {
    uint32_t a;
    asm("{ .reg .u64 t; cvta.to.shared.u64 t, %1; cvt.u32.u64 %0, t; }"
        : "=r"(a) : "l"(p));
    return a;
}

#define CP_ASYNC16(dst, src) \
    asm volatile("cp.async.cg.shared.global [%0], [%1], 16;" :: "r"(dst), "l"(src))
#define CP_COMMIT() asm volatile("cp.async.commit_group;")
#define CP_WAIT1()  asm volatile("cp.async.wait_group 1;")

#define LDSM_X4(r0, r1, r2, r3, addr) \
    asm volatile("ldmatrix.sync.aligned.m8n8.x4.shared.b16 {%0,%1,%2,%3}, [%4];" \
                 : "=r"(r0), "=r"(r1), "=r"(r2), "=r"(r3) : "r"(addr))
#define LDSM_X4_T(r0, r1, r2, r3, addr) \
    asm volatile("ldmatrix.sync.aligned.m8n8.x4.trans.shared.b16 {%0,%1,%2,%3}, [%4];" \
                 : "=r"(r0), "=r"(r1), "=r"(r2), "=r"(r3) : "r"(addr))

#define MMA_16816(d, a, b0, b1) \
    asm volatile( \
        "mma.sync.aligned.m16n8k16.row.col.f32.f16.f16.f32 " \
        "{%0,%1,%2,%3}, {%4,%5,%6,%7}, {%8,%9}, {%0,%1,%2,%3};" \
        : "+f"((d)[0]), "+f"((d)[1]), "+f"((d)[2]), "+f"((d)[3]) \
        : "r"((a)[0]), "r"((a)[1]), "r"((a)[2]), "r"((a)[3]), \
          "r"(b0), "r"(b1))

// ---------------------------------------------------------------------------
// fp32 -> fp16 prepass for x, w1, w3 (w2 is converted inside GEMM1).
// 16 floats per thread: 4 independent float4 loads (high MLP) + 2 uint4 stores.
// ---------------------------------------------------------------------------
__global__ void f2h3_kernel(const float* __restrict__ x,
                            const float* __restrict__ w1,
                            const float* __restrict__ w3,
                            __half* __restrict__ xh,
                            __half* __restrict__ w1h,
                            __half* __restrict__ w3h)
{
    constexpr long nx = (long)MTOT * D_;     // 16,777,216
    constexpr long nw = (long)4 * D_ * H_;   //  8,388,608
    long i = ((long)blockIdx.x * 256 + threadIdx.x) * 16;
    const float* s;
    __half* d;
    if (i < nx)           { s = x;  d = xh;  }
    else if (i < nx + nw) { s = w1; d = w1h; i -= nx; }
    else                  { s = w3; d = w3h; i -= nx + nw; }

    float4 v0 = *(const float4*)(s + i);
    float4 v1 = *(const float4*)(s + i + 4);
    float4 v2 = *(const float4*)(s + i + 8);
    float4 v3 = *(const float4*)(s + i + 12);

    __half2 a0 = __floats2half2_rn(v0.x, v0.y);
    __half2 a1 = __floats2half2_rn(v0.z, v0.w);
    __half2 a2 = __floats2half2_rn(v1.x, v1.y);
    __half2 a3 = __floats2half2_rn(v1.z, v1.w);
    __half2 a4 = __floats2half2_rn(v2.x, v2.y);
    __half2 a5 = __floats2half2_rn(v2.z, v2.w);
    __half2 a6 = __floats2half2_rn(v3.x, v3.y);
    __half2 a7 = __floats2half2_rn(v3.z, v3.w);

    uint4 r0, r1;
    r0.x = *(const uint32_t*)&a0;
    r0.y = *(const uint32_t*)&a1;
    r0.z = *(const uint32_t*)&a2;
    r0.w = *(const uint32_t*)&a3;
    r1.x = *(const uint32_t*)&a4;
    r1.y = *(const uint32_t*)&a5;
    r1.z = *(const uint32_t*)&a6;
    r1.w = *(const uint32_t*)&a7;
    *(uint4*)(d + i)     = r0;
    *(uint4*)(d + i + 8) = r1;
}

// ---------------------------------------------------------------------------
// Fused GEMM1 (R15-verbatim): h = silu(x @ w1[seg]) * (x @ w3[seg])
// Tile: 128(M) x 64(N per weight), BK=64, 3-stage cp.async pipeline.
// 8 warps = 4(M) x 2(N); warp subtile 32x32 per weight.
// PRELUDE: each CTA converts one 2048-elem slice of w2 fp32->fp16 (hidden
// under the pipeline prologue; GEMM2 launches only after this grid ends).
// ---------------------------------------------------------------------------
__global__ void __launch_bounds__(256, 2)
ffn_fused_kernel(const __half* __restrict__ X,
                 const __half* __restrict__ W1,
                 const __half* __restrict__ W3,
                 __half* __restrict__ Hout,
                 const float* __restrict__ W2f,
                 __half* __restrict__ W2h)
{
    constexpr int STAGE_B = 32768;           // A 16KB + B1 8KB + B3 8KB
    constexpr int NK = D_ / 64;              // 16

    extern __shared__ __align__(1024) char smem[];
    const uint32_t sbase = smem_u32(smem);

    const int tid = threadIdx.x, lane = tid & 31, wid = tid >> 5;
    const int wm = wid >> 1, wn = wid & 1;
    const int m0 = blockIdx.y * 128, n0 = blockIdx.x * 64;
    const int seg = (m0 % N_) / SEGLEN;

    const __half* gW1 = W1 + (size_t)seg * D_ * H_;
    const __half* gW3 = W3 + (size_t)seg * D_ * H_;

    auto load_stage = [&](int kt, int slot) {
        const uint32_t st = sbase + slot * STAGE_B;
        #pragma unroll
        for (int j = 0; j < 8; ++j) {
            const int id = tid + j * 256;
            const __half* src;
            uint32_t dst;
            if (id < 1024) {                       // A: x tile [128][64]
                const int r = id >> 3, c = id & 7;
                src = X + (size_t)(m0 + r) * D_ + kt * 64 + c * 8;
                dst = st + r * 128 + ((c ^ (r & 7)) << 4);
            } else {                               // B: weights [64][64] each
                const int id2 = id - 1024;
                const int w = id2 >> 9, k = (id2 >> 3) & 63, c = id2 & 7;
                const __half* wb = w ? gW3 : gW1;
                src = wb + (size_t)(kt * 64 + k) * H_ + n0 + c * 8;
                dst = st + 16384 + w * 8192 + k * 128 + ((c ^ (k & 7)) << 4);
            }
            CP_ASYNC16(dst, src);
        }
        CP_COMMIT();
    };

    load_stage(0, 0);
    load_stage(1, 1);

    // ---- w2 conversion prelude: one 2048-elem slice per CTA ---------------
    // grid = (32, 128) -> 4096 CTAs x 256 thr x 8 elems = 8,388,608 = |w2|.
    // Issued after the cp.asyncs so the LDG latency hides under the prologue.
    {
        const int bid = blockIdx.y * 32 + blockIdx.x;
        const long i = ((long)bid * 256 + tid) * 8;
        float4 v0 = *(const float4*)(W2f + i);
        float4 v1 = *(const float4*)(W2f + i + 4);
        __half2 a0 = __floats2half2_rn(v0.x, v0.y);
        __half2 a1 = __floats2half2_rn(v0.z, v0.w);
        __half2 a2 = __floats2half2_rn(v1.x, v1.y);
        __half2 a3 = __floats2half2_rn(v1.z, v1.w);
        uint4 r;
        r.x = *(const uint32_t*)&a0;
        r.y = *(const uint32_t*)&a1;
        r.z = *(const uint32_t*)&a2;
        r.w = *(const uint32_t*)&a3;
        *(uint4*)(W2h + i) = r;
    }

    const int lrow = ((lane >> 3) & 1) * 8 + (lane & 7);
    const int hi = lane >> 4;
    const int sw = lrow & 7;

    float acc[2][2][4][4];
    #pragma unroll
    for (int w = 0; w < 2; ++w)
        #pragma unroll
        for (int mf = 0; mf < 2; ++mf)
            #pragma unroll
            for (int nf = 0; nf < 4; ++nf)
                #pragma unroll
                for (int e = 0; e < 4; ++e) acc[w][mf][nf][e] = 0.0f;

    for (int kt = 0; kt < NK; ++kt) {
        CP_WAIT1();
        __syncthreads();
        if (kt + 2 < NK) load_stage(kt + 2, (kt + 2) % 3);
        else CP_COMMIT();

        const uint32_t stA = sbase + (kt % 3) * STAGE_B;
        const uint32_t stB = stA + 16384;

        #pragma unroll
        for (int kk = 0; kk < 4; ++kk) {
            uint32_t a[2][4];
            #pragma unroll
            for (int mf = 0; mf < 2; ++mf) {
                const int r = wm * 32 + mf * 16 + lrow;
                const uint32_t ad =
                    stA + r * 128 + (((kk * 2 + hi) ^ sw) << 4);
                LDSM_X4(a[mf][0], a[mf][1], a[mf][2], a[mf][3], ad);
            }
            uint32_t b[2][2][4];
            #pragma unroll
            for (int w = 0; w < 2; ++w)
                #pragma unroll
                for (int j = 0; j < 2; ++j) {
                    const int krow = kk * 16 + lrow;
                    const int nchunk = wn * 4 + j * 2 + hi;
                    const uint32_t bd = stB + w * 8192 + krow * 128 +
                                        ((nchunk ^ sw) << 4);
                    LDSM_X4_T(b[w][j][0], b[w][j][1], b[w][j][2], b[w][j][3], bd);
                }
            #pragma unroll
            for (int w = 0; w < 2; ++w)
                #pragma unroll
                for (int mf = 0; mf < 2; ++mf)
                    #pragma unroll
                    for (int nf = 0; nf < 4; ++nf)
                        MMA_16816(acc[w][mf][nf], a[mf],
                                  b[w][nf >> 1][(nf & 1) * 2],
                                  b[w][nf >> 1][(nf & 1) * 2 + 1]);
        }
    }

    // epilogue: silu(acc[0]) * acc[1] -> fp16
    #pragma unroll
    for (int mf = 0; mf < 2; ++mf)
        #pragma unroll
        for (int nf = 0; nf < 4; ++nf)
            #pragma unroll
            for (int ep = 0; ep < 2; ++ep) {
                const int r = m0 + wm * 32 + mf * 16 + (lane >> 2) + ep * 8;
                const int c = n0 + wn * 32 + nf * 8 + (lane & 3) * 2;
                const float g0 = acc[0][mf][nf][ep * 2 + 0];
                const float g1 = acc[0][mf][nf][ep * 2 + 1];
                const float u0 = acc[1][mf][nf][ep * 2 + 0];
                const float u1 = acc[1][mf][nf][ep * 2 + 1];
                const float h0 = g0 * (1.0f / (1.0f + __expf(-g0))) * u0;
                const float h1 = g1 * (1.0f / (1.0f + __expf(-g1))) * u1;
                *(__half2*)(Hout + (size_t)r * H_ + c) = __floats2half2_rn(h0, h1);
            }
}

// ---------------------------------------------------------------------------
// GEMM2 (R15-verbatim): out = h @ w2[seg]  (fp32 out)
// Tile: 128(M) x 128(N), BK=64, 3-stage pipeline.
// 8 warps = 2(M) x 4(N); warp subtile 64x32.
// ---------------------------------------------------------------------------
__global__ void __launch_bounds__(256, 2)
gemm2_kernel(const __half* __restrict__ Hin,
             const __half* __restrict__ W2,
             float* __restrict__ Out)
{
    constexpr int STAGE_B = 32768;           // A 16KB + B 16KB
    constexpr int NK = H_ / 64;              // 32

    extern __shared__ __align__(1024) char smem[];
    const uint32_t sbase = smem_u32(smem);

    const int tid = threadIdx.x, lane = tid & 31, wid = tid >> 5;
    const int wm = wid >> 2, wn = wid & 3;
    const int m0 = blockIdx.y * 128, n0 = blockIdx.x * 128;
    const int seg = (m0 % N_) / SEGLEN;

    const __half* gW2 = W2 + (size_t)seg * H_ * D_;

    auto load_stage = [&](int kt, int slot) {
        const uint32_t st = sbase + slot * STAGE_B;
        #pragma unroll
        for (int j = 0; j < 8; ++j) {
            const int id = tid + j * 256;
            const __half* src;
            uint32_t dst;
            if (id < 1024) {                       // A: h tile [128][64]
                const int r = id >> 3, c = id & 7;
                src = Hin + (size_t)(m0 + r) * H_ + kt * 64 + c * 8;
                dst = st + r * 128 + ((c ^ (r & 7)) << 4);
            } else {                               // B: w2 tile [64][128]
                const int id2 = id - 1024;
                const int k = id2 >> 4, c = id2 & 15;
                src = gW2 + (size_t)(kt * 64 + k) * D_ + n0 + c * 8;
                dst = st + 16384 + k * 256 + ((c ^ (k & 7)) << 4);
            }
            CP_ASYNC16(dst, src);
        }
        CP_COMMIT();
    };

    const int lrow = ((lane >> 3) & 1) * 8 + (lane & 7);
    const int hi = lane >> 4;
    const int sw = lrow & 7;

    float acc[4][4][4];
    #pragma unroll
    for (int mf = 0; mf < 4; ++mf)
        #pragma unroll
        for (int nf = 0; nf < 4; ++nf)
            #pragma unroll
            for (int e = 0; e < 4; ++e) acc[mf][nf][e] = 0.0f;

    load_stage(0, 0);
    load_stage(1, 1);

    for (int kt = 0; kt < NK; ++kt) {
        CP_WAIT1();
        __syncthreads();
        if (kt + 2 < NK) load_stage(kt + 2, (kt + 2) % 3);
        else CP_COMMIT();

        const uint32_t stA = sbase + (kt % 3) * STAGE_B;
        const uint32_t stB = stA + 16384;

        #pragma unroll
        for (int kk = 0; kk < 4; ++kk) {
            uint32_t a[4][4];
            #pragma unroll
            for (int mf = 0; mf < 4; ++mf) {
                const int r = wm * 64 + mf * 16 + lrow;
                const uint32_t ad =
                    stA + r * 128 + (((kk * 2 + hi) ^ sw) << 4);
                LDSM_X4(a[mf][0], a[mf][1], a[mf][2], a[mf][3], ad);
            }
            uint32_t b[2][4];
            #pragma unroll
            for (int j = 0; j < 2; ++j) {
                const int krow = kk * 16 + lrow;
                const int nchunk = wn * 4 + j * 2 + hi;
                const uint32_t bd = stB + krow * 256 + ((nchunk ^ sw) << 4);
                LDSM_X4_T(b[j][0], b[j][1], b[j][2], b[j][3], bd);
            }
            #pragma unroll
            for (int mf = 0; mf < 4; ++mf)
                #pragma unroll
                for (int nf = 0; nf < 4; ++nf)
                    MMA_16816(acc[mf][nf], a[mf],
                              b[nf >> 1][(nf & 1) * 2],
                              b[nf >> 1][(nf & 1) * 2 + 1]);
        }
    }

    #pragma unroll
    for (int mf = 0; mf < 4; ++mf)
        #pragma unroll
        for (int nf = 0; nf < 4; ++nf)
            #pragma unroll
            for (int ep = 0; ep < 2; ++ep) {
                const int r = m0 + wm * 64 + mf * 16 + (lane >> 2) + ep * 8;
                const int c = n0 + wn * 32 + nf * 8 + (lane & 3) * 2;
                float2 v = make_float2(acc[mf][nf][ep * 2 + 0],
                                       acc[mf][nf][ep * 2 + 1]);
                *(float2*)(Out + (size_t)r * D_ + c) = v;
            }
}

// ---------------------------------------------------------------------------
extern "C" void kernel_launch(void* const* d_in, const int* in_sizes, int n_in,
                              void* d_out, int out_size)
{
    const float* x  = (const float*)d_in[0];
    const float* w1 = (const float*)d_in[1];
    const float* w3 = (const float*)d_in[2];
    const float* w2 = (const float*)d_in[3];
    float* out = (float*)d_out;

    __half *xh, *w1h, *w3h, *w2h, *h;
    cudaGetSymbolAddress((void**)&xh,  g_xh);
    cudaGetSymbolAddress((void**)&w1h, g_w1h);
    cudaGetSymbolAddress((void**)&w3h, g_w3h);
    cudaGetSymbolAddress((void**)&w2h, g_w2h);
    cudaGetSymbolAddress((void**)&h,   g_h);

    constexpr int SMEM = 3 * 32768;   // 96 KB
    cudaFuncSetAttribute(ffn_fused_kernel,
                         cudaFuncAttributeMaxDynamicSharedMemorySize, SMEM);
    cudaFuncSetAttribute(gemm2_kernel,
                         cudaFuncAttributeMaxDynamicSharedMemorySize, SMEM);

    // prepass converts x, w1, w3 only (w2 handled inside GEMM1); 16 f/thread
    constexpr long TOT16 = ((long)MTOT * D_ + 2L * 4 * D_ * H_) / 16;
    f2h3_kernel<<<(unsigned)(TOT16 / 256), 256>>>(x, w1, w3, xh, w1h, w3h);

    // h = silu(x @ w1[seg]) * (x @ w3[seg])  + embedded w2 fp32->fp16
    ffn_fused_kernel<<<dim3(H_ / 64, MTOT / 128), 256, SMEM>>>(
        xh, w1h, w3h, h, w2, w2h);
    // out = h @ w2[seg]
    gemm2_kernel<<<dim3(D_ / 128, MTOT / 128), 256, SMEM>>>(h, w2h, out);
}

// round 17
// speedup vs baseline: 1.0020x; 1.0020x over previous
#include <cuda_runtime.h>
#include <cuda_fp16.h>
#include <cstdint>
#include <cstddef>

// ---------------------------------------------------------------------------
// Problem constants
// ---------------------------------------------------------------------------
constexpr int B_ = 8, N_ = 2048, D_ = 1024, H_ = 2048;
constexpr int MTOT = B_ * N_;      // 16384
constexpr int SEGLEN = 512;

// Scratch (device globals; allocations forbidden)
__device__ __half g_xh [(size_t)MTOT * D_];
__device__ __half g_w1h[(size_t)4 * D_ * H_];
__device__ __half g_w3h[(size_t)4 * D_ * H_];
__device__ __half g_w2h[(size_t)4 * H_ * D_];
__device__ __half g_h  [(size_t)MTOT * H_];

// ---------------------------------------------------------------------------
// Helpers
// ---------------------------------------------------------------------------
__device__ __forceinline__ uint32_t smem_u32(const void* p) {
    uint32_t a;
    asm("{ .reg .u64 t; cvta.to.shared.u64 t, %1; cvt.u32.u64 %0, t; }"
        : "=r"(a) : "l"(p));
    return a;
}

#define CP_ASYNC16(dst, src) \
    asm volatile("cp.async.cg.shared.global [%0], [%1], 16;" :: "r"(dst), "l"(src))
#define CP_COMMIT() asm volatile("cp.async.commit_group;")
#define CP_WAIT1()  asm volatile("cp.async.wait_group 1;")

#define LDSM_X4(r0, r1, r2, r3, addr) \
    asm volatile("ldmatrix.sync.aligned.m8n8.x4.shared.b16 {%0,%1,%2,%3}, [%4];" \
                 : "=r"(r0), "=r"(r1), "=r"(r2), "=r"(r3) : "r"(addr))
#define LDSM_X4_T(r0, r1, r2, r3, addr) \
    asm volatile("ldmatrix.sync.aligned.m8n8.x4.trans.shared.b16 {%0,%1,%2,%3}, [%4];" \
                 : "=r"(r0), "=r"(r1), "=r"(r2), "=r"(r3) : "r"(addr))

#define MMA_16816(d, a, b0, b1) \
    asm volatile( \
        "mma.sync.aligned.m16n8k16.row.col.f32.f16.f16.f32 " \
        "{%0,%1,%2,%3}, {%4,%5,%6,%7}, {%8,%9}, {%0,%1,%2,%3};" \
        : "+f"((d)[0]), "+f"((d)[1]), "+f"((d)[2]), "+f"((d)[3]) \
        : "r"((a)[0]), "r"((a)[1]), "r"((a)[2]), "r"((a)[3]), \
          "r"(b0), "r"(b1))

// Streaming (evict-first) stores — keep L2 for GEMM operands.
#define STG_CS_U32(addr, v) \
    asm volatile("st.global.cs.u32 [%0], %1;" :: "l"(addr), "r"(v) : "memory")
#define STG_CS_F32X2(addr, v0, v1) \
    asm volatile("st.global.cs.v2.f32 [%0], {%1, %2};" \
                 :: "l"(addr), "f"(v0), "f"(v1) : "memory")

// ---------------------------------------------------------------------------
// fp32 -> fp16 prepass for x, w1, w3 (w2 is converted inside GEMM1).
// 16 floats per thread: 4 independent float4 loads + 2 uint4 stores.
// ---------------------------------------------------------------------------
__global__ void f2h3_kernel(const float* __restrict__ x,
                            const float* __restrict__ w1,
                            const float* __restrict__ w3,
                            __half* __restrict__ xh,
                            __half* __restrict__ w1h,
                            __half* __restrict__ w3h)
{
    constexpr long nx = (long)MTOT * D_;     // 16,777,216
    constexpr long nw = (long)4 * D_ * H_;   //  8,388,608
    long i = ((long)blockIdx.x * 256 + threadIdx.x) * 16;
    const float* s;
    __half* d;
    if (i < nx)           { s = x;  d = xh;  }
    else if (i < nx + nw) { s = w1; d = w1h; i -= nx; }
    else                  { s = w3; d = w3h; i -= nx + nw; }

    float4 v0 = *(const float4*)(s + i);
    float4 v1 = *(const float4*)(s + i + 4);
    float4 v2 = *(const float4*)(s + i + 8);
    float4 v3 = *(const float4*)(s + i + 12);

    __half2 a0 = __floats2half2_rn(v0.x, v0.y);
    __half2 a1 = __floats2half2_rn(v0.z, v0.w);
    __half2 a2 = __floats2half2_rn(v1.x, v1.y);
    __half2 a3 = __floats2half2_rn(v1.z, v1.w);
    __half2 a4 = __floats2half2_rn(v2.x, v2.y);
    __half2 a5 = __floats2half2_rn(v2.z, v2.w);
    __half2 a6 = __floats2half2_rn(v3.x, v3.y);
    __half2 a7 = __floats2half2_rn(v3.z, v3.w);

    uint4 r0, r1;
    r0.x = *(const uint32_t*)&a0;
    r0.y = *(const uint32_t*)&a1;
    r0.z = *(const uint32_t*)&a2;
    r0.w = *(const uint32_t*)&a3;
    r1.x = *(const uint32_t*)&a4;
    r1.y = *(const uint32_t*)&a5;
    r1.z = *(const uint32_t*)&a6;
    r1.w = *(const uint32_t*)&a7;
    *(uint4*)(d + i)     = r0;
    *(uint4*)(d + i + 8) = r1;
}

// ---------------------------------------------------------------------------
// Fused GEMM1: h = silu(x @ w1[seg]) * (x @ w3[seg])
// Tile: 128(M) x 64(N per weight), BK=64, 3-stage cp.async pipeline.
// 8 warps = 4(M) x 2(N); warp subtile 32x32 per weight.
// PRELUDE: each CTA converts one 2048-elem slice of w2 fp32->fp16.
// Epilogue stores h with .cs (streaming) to preserve L2 for operands.
// ---------------------------------------------------------------------------
__global__ void __launch_bounds__(256, 2)
ffn_fused_kernel(const __half* __restrict__ X,
                 const __half* __restrict__ W1,
                 const __half* __restrict__ W3,
                 __half* __restrict__ Hout,
                 const float* __restrict__ W2f,
                 __half* __restrict__ W2h)
{
    constexpr int STAGE_B = 32768;           // A 16KB + B1 8KB + B3 8KB
    constexpr int NK = D_ / 64;              // 16

    extern __shared__ __align__(1024) char smem[];
    const uint32_t sbase = smem_u32(smem);

    const int tid = threadIdx.x, lane = tid & 31, wid = tid >> 5;
    const int wm = wid >> 1, wn = wid & 1;
    const int m0 = blockIdx.y * 128, n0 = blockIdx.x * 64;
    const int seg = (m0 % N_) / SEGLEN;

    const __half* gW1 = W1 + (size_t)seg * D_ * H_;
    const __half* gW3 = W3 + (size_t)seg * D_ * H_;

    auto load_stage = [&](int kt, int slot) {
        const uint32_t st = sbase + slot * STAGE_B;
        #pragma unroll
        for (int j = 0; j < 8; ++j) {
            const int id = tid + j * 256;
            const __half* src;
            uint32_t dst;
            if (id < 1024) {                       // A: x tile [128][64]
                const int r = id >> 3, c = id & 7;
                src = X + (size_t)(m0 + r) * D_ + kt * 64 + c * 8;
                dst = st + r * 128 + ((c ^ (r & 7)) << 4);
            } else {                               // B: weights [64][64] each
                const int id2 = id - 1024;
                const int w = id2 >> 9, k = (id2 >> 3) & 63, c = id2 & 7;
                const __half* wb = w ? gW3 : gW1;
                src = wb + (size_t)(kt * 64 + k) * H_ + n0 + c * 8;
                dst = st + 16384 + w * 8192 + k * 128 + ((c ^ (k & 7)) << 4);
            }
            CP_ASYNC16(dst, src);
        }
        CP_COMMIT();
    };

    load_stage(0, 0);
    load_stage(1, 1);

    // ---- w2 conversion prelude: one 2048-elem slice per CTA ---------------
    {
        const int bid = blockIdx.y * 32 + blockIdx.x;
        const long i = ((long)bid * 256 + tid) * 8;
        float4 v0 = *(const float4*)(W2f + i);
        float4 v1 = *(const float4*)(W2f + i + 4);
        __half2 a0 = __floats2half2_rn(v0.x, v0.y);
        __half2 a1 = __floats2half2_rn(v0.z, v0.w);
        __half2 a2 = __floats2half2_rn(v1.x, v1.y);
        __half2 a3 = __floats2half2_rn(v1.z, v1.w);
        uint4 r;
        r.x = *(const uint32_t*)&a0;
        r.y = *(const uint32_t*)&a1;
        r.z = *(const uint32_t*)&a2;
        r.w = *(const uint32_t*)&a3;
        *(uint4*)(W2h + i) = r;
    }

    const int lrow = ((lane >> 3) & 1) * 8 + (lane & 7);
    const int hi = lane >> 4;
    const int sw = lrow & 7;

    float acc[2][2][4][4];
    #pragma unroll
    for (int w = 0; w < 2; ++w)
        #pragma unroll
        for (int mf = 0; mf < 2; ++mf)
            #pragma unroll
            for (int nf = 0; nf < 4; ++nf)
                #pragma unroll
                for (int e = 0; e < 4; ++e) acc[w][mf][nf][e] = 0.0f;

    for (int kt = 0; kt < NK; ++kt) {
        CP_WAIT1();
        __syncthreads();
        if (kt + 2 < NK) load_stage(kt + 2, (kt + 2) % 3);
        else CP_COMMIT();

        const uint32_t stA = sbase + (kt % 3) * STAGE_B;
        const uint32_t stB = stA + 16384;

        #pragma unroll
        for (int kk = 0; kk < 4; ++kk) {
            uint32_t a[2][4];
            #pragma unroll
            for (int mf = 0; mf < 2; ++mf) {
                const int r = wm * 32 + mf * 16 + lrow;
                const uint32_t ad =
                    stA + r * 128 + (((kk * 2 + hi) ^ sw) << 4);
                LDSM_X4(a[mf][0], a[mf][1], a[mf][2], a[mf][3], ad);
            }
            uint32_t b[2][2][4];
            #pragma unroll
            for (int w = 0; w < 2; ++w)
                #pragma unroll
                for (int j = 0; j < 2; ++j) {
                    const int krow = kk * 16 + lrow;
                    const int nchunk = wn * 4 + j * 2 + hi;
                    const uint32_t bd = stB + w * 8192 + krow * 128 +
                                        ((nchunk ^ sw) << 4);
                    LDSM_X4_T(b[w][j][0], b[w][j][1], b[w][j][2], b[w][j][3], bd);
                }
            #pragma unroll
            for (int w = 0; w < 2; ++w)
                #pragma unroll
                for (int mf = 0; mf < 2; ++mf)
                    #pragma unroll
                    for (int nf = 0; nf < 4; ++nf)
                        MMA_16816(acc[w][mf][nf], a[mf],
                                  b[w][nf >> 1][(nf & 1) * 2],
                                  b[w][nf >> 1][(nf & 1) * 2 + 1]);
        }
    }

    // epilogue: silu(acc[0]) * acc[1] -> fp16, streaming store
    #pragma unroll
    for (int mf = 0; mf < 2; ++mf)
        #pragma unroll
        for (int nf = 0; nf < 4; ++nf)
            #pragma unroll
            for (int ep = 0; ep < 2; ++ep) {
                const int r = m0 + wm * 32 + mf * 16 + (lane >> 2) + ep * 8;
                const int c = n0 + wn * 32 + nf * 8 + (lane & 3) * 2;
                const float g0 = acc[0][mf][nf][ep * 2 + 0];
                const float g1 = acc[0][mf][nf][ep * 2 + 1];
                const float u0 = acc[1][mf][nf][ep * 2 + 0];
                const float u1 = acc[1][mf][nf][ep * 2 + 1];
                const float h0 = g0 * (1.0f / (1.0f + __expf(-g0))) * u0;
                const float h1 = g1 * (1.0f / (1.0f + __expf(-g1))) * u1;
                __half2 hv = __floats2half2_rn(h0, h1);
                STG_CS_U32(Hout + (size_t)r * H_ + c, *(const uint32_t*)&hv);
            }
}

// ---------------------------------------------------------------------------
// GEMM2: out = h @ w2[seg]  (fp32 out, streaming store)
// Tile: 128(M) x 128(N), BK=64, 3-stage pipeline.
// 8 warps = 2(M) x 4(N); warp subtile 64x32.
// ---------------------------------------------------------------------------
__global__ void __launch_bounds__(256, 2)
gemm2_kernel(const __half* __restrict__ Hin,
             const __half* __restrict__ W2,
             float* __restrict__ Out)
{
    constexpr int STAGE_B = 32768;           // A 16KB + B 16KB
    constexpr int NK = H_ / 64;              // 32

    extern __shared__ __align__(1024) char smem[];
    const uint32_t sbase = smem_u32(smem);

    const int tid = threadIdx.x, lane = tid & 31, wid = tid >> 5;
    const int wm = wid >> 2, wn = wid & 3;
    const int m0 = blockIdx.y * 128, n0 = blockIdx.x * 128;
    const int seg = (m0 % N_) / SEGLEN;

    const __half* gW2 = W2 + (size_t)seg * H_ * D_;

    auto load_stage = [&](int kt, int slot) {
        const uint32_t st = sbase + slot * STAGE_B;
        #pragma unroll
        for (int j = 0; j < 8; ++j) {
            const int id = tid + j * 256;
            const __half* src;
            uint32_t dst;
            if (id < 1024) {                       // A: h tile [128][64]
                const int r = id >> 3, c = id & 7;
                src = Hin + (size_t)(m0 + r) * H_ + kt * 64 + c * 8;
                dst = st + r * 128 + ((c ^ (r & 7)) << 4);
            } else {                               // B: w2 tile [64][128]
                const int id2 = id - 1024;
                const int k = id2 >> 4, c = id2 & 15;
                src = gW2 + (size_t)(kt * 64 + k) * D_ + n0 + c * 8;
                dst = st + 16384 + k * 256 + ((c ^ (k & 7)) << 4);
            }
            CP_ASYNC16(dst, src);
        }
        CP_COMMIT();
    };

    const int lrow = ((lane >> 3) & 1) * 8 + (lane & 7);
    const int hi = lane >> 4;
    const int sw = lrow & 7;

    float acc[4][4][4];
    #pragma unroll
    for (int mf = 0; mf < 4; ++mf)
        #pragma unroll
        for (int nf = 0; nf < 4; ++nf)
            #pragma unroll
            for (int e = 0; e < 4; ++e) acc[mf][nf][e] = 0.0f;

    load_stage(0, 0);
    load_stage(1, 1);

    for (int kt = 0; kt < NK; ++kt) {
        CP_WAIT1();
        __syncthreads();
        if (kt + 2 < NK) load_stage(kt + 2, (kt + 2) % 3);
        else CP_COMMIT();

        const uint32_t stA = sbase + (kt % 3) * STAGE_B;
        const uint32_t stB = stA + 16384;

        #pragma unroll
        for (int kk = 0; kk < 4; ++kk) {
            uint32_t a[4][4];
            #pragma unroll
            for (int mf = 0; mf < 4; ++mf) {
                const int r = wm * 64 + mf * 16 + lrow;
                const uint32_t ad =
                    stA + r * 128 + (((kk * 2 + hi) ^ sw) << 4);
                LDSM_X4(a[mf][0], a[mf][1], a[mf][2], a[mf][3], ad);
            }
            uint32_t b[2][4];
            #pragma unroll
            for (int j = 0; j < 2; ++j) {
                const int krow = kk * 16 + lrow;
                const int nchunk = wn * 4 + j * 2 + hi;
                const uint32_t bd = stB + krow * 256 + ((nchunk ^ sw) << 4);
                LDSM_X4_T(b[j][0], b[j][1], b[j][2], b[j][3], bd);
            }
            #pragma unroll
            for (int mf = 0; mf < 4; ++mf)
                #pragma unroll
                for (int nf = 0; nf < 4; ++nf)
                    MMA_16816(acc[mf][nf], a[mf],
                              b[nf >> 1][(nf & 1) * 2],
                              b[nf >> 1][(nf & 1) * 2 + 1]);
        }
    }

    #pragma unroll
    for (int mf = 0; mf < 4; ++mf)
        #pragma unroll
        for (int nf = 0; nf < 4; ++nf)
            #pragma unroll
            for (int ep = 0; ep < 2; ++ep) {
                const int r = m0 + wm * 64 + mf * 16 + (lane >> 2) + ep * 8;
                const int c = n0 + wn * 32 + nf * 8 + (lane & 3) * 2;
                STG_CS_F32X2(Out + (size_t)r * D_ + c,
                             acc[mf][nf][ep * 2 + 0],
                             acc[mf][nf][ep * 2 + 1]);
            }
}

// ---------------------------------------------------------------------------
extern "C" void kernel_launch(void* const* d_in, const int* in_sizes, int n_in,
                              void* d_out, int out_size)
{
    const float* x  = (const float*)d_in[0];
    const float* w1 = (const float*)d_in[1];
    const float* w3 = (const float*)d_in[2];
    const float* w2 = (const float*)d_in[3];
    float* out = (float*)d_out;

    __half *xh, *w1h, *w3h, *w2h, *h;
    cudaGetSymbolAddress((void**)&xh,  g_xh);
    cudaGetSymbolAddress((void**)&w1h, g_w1h);
    cudaGetSymbolAddress((void**)&w3h, g_w3h);
    cudaGetSymbolAddress((void**)&w2h, g_w2h);
    cudaGetSymbolAddress((void**)&h,   g_h);

    constexpr int SMEM = 3 * 32768;   // 96 KB
    cudaFuncSetAttribute(ffn_fused_kernel,
                         cudaFuncAttributeMaxDynamicSharedMemorySize, SMEM);
    cudaFuncSetAttribute(gemm2_kernel,
                         cudaFuncAttributeMaxDynamicSharedMemorySize, SMEM);

    // prepass converts x, w1, w3 only (w2 handled inside GEMM1); 16 f/thread
    constexpr long TOT16 = ((long)MTOT * D_ + 2L * 4 * D_ * H_) / 16;
    f2h3_kernel<<<(unsigned)(TOT16 / 256), 256>>>(x, w1, w3, xh, w1h, w3h);

    // h = silu(x @ w1[seg]) * (x @ w3[seg])  + embedded w2 fp32->fp16
    ffn_fused_kernel<<<dim3(H_ / 64, MTOT / 128), 256, SMEM>>>(
        xh, w1h, w3h, h, w2, w2h);
    // out = h @ w2[seg]
    gemm2_kernel<<<dim3(D_ / 128, MTOT / 128), 256, SMEM>>>(h, w2h, out);
}